// round 14
// baseline (speedup 1.0000x reference)
#include <cuda_runtime.h>
#include <cuda_fp16.h>
#include <cstdint>

// ============================================================
// 3-layer SNN. B=16384, H=512, 127 steps.
// R14 = R13 + two column-tiles per CTA with a seamless cp.async ring across
// the tile boundary (grid 128x2, 32-chunk ring, tile-1 fill hidden under
// tile-0 epilogue). Per-output MMA order unchanged -> bit-identical rel_err.
//  - overlapped setup (W-prep on s2, spikes0 tail on s3, capture-fork safe)
//  - forked-stream t-loop: g2(t) on s2 overlaps g1(t+1)
//  - 2 exact fp16 W-splits on mma.sync m16n8k16, fp32 accum
// ============================================================

constexpr int NSTEP = 127;
constexpr int TSPLIT = 8;              // spikes0 split point
constexpr int NELEM = 16384 * 512;

__device__ float g_h0[NELEM];
__device__ float g_mc[NELEM];          // layer-0 membrane carry at t=TSPLIT
__device__ float g_s1[NELEM];
__device__ float g_m1[NELEM];
__device__ float g_s2[NELEM];
__device__ __half g_spk0all[(size_t)NSTEP * NELEM];   // 2.13GB
__device__ __half g_spk1a[NELEM];
__device__ __half g_spk1b[NELEM];
__device__ __half g_W1t[2][512 * 512];   // [split][N][K] K-contiguous
__device__ __half g_W2t[2][512 * 512];

// ---- PTX helpers (sm_80-class, valid at sm_103 base target) ----
__device__ __forceinline__ uint32_t smem_to_u32(const void* p) {
    uint32_t a;
    asm("{ .reg .u64 t; cvta.to.shared.u64 t, %1; cvt.u32.u64 %0, t; }"
        : "=r"(a) : "l"(p));
    return a;
}
__device__ __forceinline__ void cp16(uint32_t dst, const void* src) {
    asm volatile("cp.async.cg.shared.global [%0], [%1], 16;"
                 :: "r"(dst), "l"(src) : "memory");
}
#define CP_COMMIT() asm volatile("cp.async.commit_group;" ::: "memory")
#define CP_WAIT(N)  asm volatile("cp.async.wait_group %0;" :: "n"(N) : "memory")
__device__ __forceinline__ void l2_prefetch(const void* p) {
    asm volatile("prefetch.global.L2 [%0];" :: "l"(p));
}

__device__ __forceinline__ void ldm4(uint32_t& r0, uint32_t& r1, uint32_t& r2,
                                     uint32_t& r3, uint32_t addr) {
    asm volatile("ldmatrix.sync.aligned.m8n8.x4.shared.b16 {%0,%1,%2,%3}, [%4];"
                 : "=r"(r0), "=r"(r1), "=r"(r2), "=r"(r3) : "r"(addr));
}
__device__ __forceinline__ void mma16816(float* c, const uint32_t* a,
                                         uint32_t b0, uint32_t b1) {
    asm volatile(
        "mma.sync.aligned.m16n8k16.row.col.f32.f16.f16.f32 "
        "{%0,%1,%2,%3}, {%4,%5,%6,%7}, {%8,%9}, {%0,%1,%2,%3};"
        : "+f"(c[0]), "+f"(c[1]), "+f"(c[2]), "+f"(c[3])
        : "r"(a[0]), "r"(a[1]), "r"(a[2]), "r"(a[3]), "r"(b0), "r"(b1));
}
#define SWZ64(x) ((x) ^ (((x) >> 3) & 0x30))

// ============================================================
// one-time kernels
// ============================================================
__global__ void zero_kernel(float4* __restrict__ out) {
    int i = blockIdx.x * blockDim.x + threadIdx.x;
    float4 z = make_float4(0.f, 0.f, 0.f, 0.f);
    ((float4*)g_s1)[i] = z;
    ((float4*)g_m1)[i] = z;
    ((float4*)g_s2)[i] = z;
    out[i] = z;
}

// exact 2-way fp16 split + transpose of W [512K x 512N] -> Wt[2][N][K]
template <int WHICH>
__global__ void prep_kernel(const float* __restrict__ Wsrc) {
    int idx = blockIdx.x * blockDim.x + threadIdx.x;  // over 512*512
    int k = idx >> 9, n = idx & 511;
    float w = Wsrc[idx];
    __half hi = __float2half_rn(w);
    __half lo = __float2half_rn(w - __half2float(hi));
    __half (*dst)[512 * 512] = (WHICH == 1) ? g_W1t : g_W2t;
    int t = n * 512 + k;
    dst[0][t] = hi;
    dst[1][t] = lo;
}

// layer-0 LIF trajectories, t in [T0, T1). PART A writes the carry;
// PART B resumes from it — identical per-element arithmetic.
template <int T0, int T1, bool WRITE_CARRY>
__global__ void spikes0_kernel() {
    int idx = blockIdx.x * blockDim.x + threadIdx.x;  // over NELEM
    float h = g_h0[idx];
    float m = (T0 == 0) ? 0.f : g_mc[idx];
#pragma unroll 1
    for (int t = T0; t < T1; t++) {
        m = 0.85f * m + h;
        bool p = m > 1.0f;
        g_spk0all[(size_t)t * NELEM + idx] = p ? __float2half(1.f)
                                               : __float2half(0.f);
        if (p) m = 0.f;
    }
    if (WRITE_CARRY) g_mc[idx] = m;
}

// ============================================================
// layer-0 drive: h0 = relu_concat(inputs) @ W0 (fp32, runs once)
// ============================================================
__global__ __launch_bounds__(256)
void gemm0_kernel(const float* __restrict__ Aext, const float* __restrict__ W) {
    constexpr int KT = 8, NK = 256 / KT;
    __shared__ float As[2][KT][128];
    __shared__ float Bs[2][KT][128];
    const int row0 = blockIdx.x * 128, col0 = blockIdx.y * 128;
    const int tid = threadIdx.x;
    const int tx = tid & 15, ty = tid >> 4;
    const int ar = tid >> 1, aq = (tid & 1) * 4;
    const int bk = tid >> 5, bj = (tid & 31) * 4;

    float acc[8][8];
#pragma unroll
    for (int i = 0; i < 8; i++)
#pragma unroll
        for (int j = 0; j < 8; j++) acc[i][j] = 0.f;

    float4 ra, rb;
    auto LOADG = [&](int k0) {
        int kk = k0 + aq;
        if (kk < 128) {
            float4 v = *(const float4*)(Aext + (size_t)(row0 + ar) * 128 + kk);
            ra.x = fmaxf(v.x, 0.f); ra.y = fmaxf(v.y, 0.f);
            ra.z = fmaxf(v.z, 0.f); ra.w = fmaxf(v.w, 0.f);
        } else {
            float4 v = *(const float4*)(Aext + (size_t)(row0 + ar) * 128 + (kk - 128));
            ra.x = fmaxf(-v.x, 0.f); ra.y = fmaxf(-v.y, 0.f);
            ra.z = fmaxf(-v.z, 0.f); ra.w = fmaxf(-v.w, 0.f);
        }
        rb = *(const float4*)(W + (size_t)(k0 + bk) * 512 + col0 + bj);
    };
    auto STORES = [&](int buf) {
        As[buf][aq + 0][ar] = ra.x; As[buf][aq + 1][ar] = ra.y;
        As[buf][aq + 2][ar] = ra.z; As[buf][aq + 3][ar] = ra.w;
        *(float4*)&Bs[buf][bk][bj] = rb;
    };

    LOADG(0); STORES(0); __syncthreads();
    for (int kt = 0; kt < NK; kt++) {
        const int buf = kt & 1;
        if (kt + 1 < NK) LOADG((kt + 1) * KT);
#pragma unroll
        for (int k = 0; k < KT; k++) {
            float4 a0 = *(const float4*)&As[buf][k][ty * 8];
            float4 a1 = *(const float4*)&As[buf][k][ty * 8 + 4];
            float4 b0 = *(const float4*)&Bs[buf][k][tx * 8];
            float4 b1 = *(const float4*)&Bs[buf][k][tx * 8 + 4];
            float av[8] = {a0.x, a0.y, a0.z, a0.w, a1.x, a1.y, a1.z, a1.w};
            float bv[8] = {b0.x, b0.y, b0.z, b0.w, b1.x, b1.y, b1.z, b1.w};
#pragma unroll
            for (int i = 0; i < 8; i++)
#pragma unroll
                for (int j = 0; j < 8; j++) acc[i][j] = fmaf(av[i], bv[j], acc[i][j]);
        }
        if (kt + 1 < NK) STORES(buf ^ 1);
        __syncthreads();
    }
    const int r0 = row0 + ty * 8, c0 = col0 + tx * 8;
#pragma unroll
    for (int i = 0; i < 8; i++) {
        size_t base = (size_t)(r0 + i) * 512 + c0;
        *(float4*)&g_h0[base]     = make_float4(acc[i][0], acc[i][1], acc[i][2], acc[i][3]);
        *(float4*)&g_h0[base + 4] = make_float4(acc[i][4], acc[i][5], acc[i][6], acc[i][7]);
    }
}

// ============================================================
// HMMA GEMM + fused LIF epilogue — TWO column-tiles per CTA.
// Grid (128, 2): CTA handles col tiles y and y+2 via one 32-chunk ring
// (16 K-chunks per tile). 4 stages x 24KB, prefetch depth 3, wait_group 2,
// one barrier per chunk; tile-1 fill hides under tile-0 epilogue.
// 8 warps, warp tile 64x32. 2 fp16 W-splits, fp32 accum.
// ============================================================
constexpr int STAGE_BYTES = 24576;
constexpr int SMEM_NEED   = 4 * STAGE_BYTES;   // 96KB -> 2 CTAs/SM

template <int MODE>
__global__ __launch_bounds__(256, 2)
void gemm_mma(const __half* __restrict__ A, __half* __restrict__ spk_out,
              float* __restrict__ Mext) {
    extern __shared__ char smem[];
    const int tid = threadIdx.x;
    const int wid = tid >> 5, lane = tid & 31;
    const int warp_m = wid & 1, warp_n = wid >> 1;
    const int row0 = blockIdx.x * 128;
    const int ybase = blockIdx.y;                   // col tiles ybase, ybase+2

    const __half* W = (MODE == 1) ? &g_W1t[0][0] : &g_W2t[0][0];
    const uint32_t sb = smem_to_u32(smem);

    // ring chunk g in [0,32): tile = g>>4, K-chunk = g&15, stage = g&3
    auto load_chunk = [&](int g) {
        const int col0 = (ybase + (g >> 4) * 2) * 128;
        const int k0 = (g & 15) * 32;
        const uint32_t ap = sb + (g & 3) * STAGE_BYTES;
        const uint32_t bp = ap + 8192;
#pragma unroll
        for (int j = 0; j < 2; j++) {                  // A: 512 x 16B
            int i = tid + j * 256;
            int r = i >> 2, q = i & 3;
            cp16(ap + SWZ64(r * 64 + q * 16),
                 A + (size_t)(row0 + r) * 512 + k0 + q * 8);
        }
#pragma unroll
        for (int j = 0; j < 4; j++) {                  // B: 2 x 512 x 16B
            int i = tid + j * 256;
            int sp = i >> 9, rem = i & 511;
            int n = rem >> 2, q = rem & 3;
            cp16(bp + sp * 8192 + SWZ64(n * 64 + q * 16),
                 W + (size_t)sp * 262144 + (size_t)(col0 + n) * 512 + k0 + q * 8);
        }
        CP_COMMIT();
    };

    load_chunk(0);
    load_chunk(1);
    load_chunk(2);

    // warm L2 with both tiles' epilogue state
    {
        const float* S = (MODE == 1) ? g_s1 : g_s2;
        const float* M = (MODE == 1) ? g_m1 : Mext;
#pragma unroll
        for (int tl = 0; tl < 2; tl++) {
            size_t pix = (size_t)(row0 + (tid >> 1)) * 512 +
                         (ybase + tl * 2) * 128 + (tid & 1) * 64;
            l2_prefetch(S + pix);  l2_prefetch(S + pix + 32);
            l2_prefetch(M + pix);  l2_prefetch(M + pix + 32);
        }
    }

    float acc[4][4][4];
#pragma unroll
    for (int mt = 0; mt < 4; mt++)
#pragma unroll
        for (int nb = 0; nb < 4; nb++)
#pragma unroll
            for (int e = 0; e < 4; e++) acc[mt][nb][e] = 0.f;

    const int mat = lane >> 3, mrr = lane & 7;

    // fused LIF epilogue for one tile, direct from mma fragments
    auto epilogue = [&](int col0) {
        float* S = (MODE == 1) ? g_s1 : g_s2;
        float* M = (MODE == 1) ? g_m1 : Mext;
        const int er = row0 + warp_m * 64 + (lane >> 2);
        const int ec = col0 + warp_n * 32 + (lane & 3) * 2;
#pragma unroll
        for (int mt = 0; mt < 4; mt++)
#pragma unroll
            for (int nb = 0; nb < 4; nb++)
#pragma unroll
                for (int hrow = 0; hrow < 2; hrow++) {
                    size_t ix = (size_t)(er + mt * 16 + hrow * 8) * 512 + ec + nb * 8;
                    float2 sv = *(const float2*)(S + ix);
                    float2 mv = *(const float2*)(M + ix);
                    float hx = acc[mt][nb][hrow * 2 + 0];
                    float hy = acc[mt][nb][hrow * 2 + 1];
                    sv.x = 0.9f * sv.x + hx;  mv.x = 0.85f * mv.x + sv.x;
                    sv.y = 0.9f * sv.y + hy;  mv.y = 0.85f * mv.y + sv.y;
                    if (MODE == 1) {
                        float px = (mv.x > 1.f) ? 1.f : 0.f;  mv.x = (mv.x > 1.f) ? 0.f : mv.x;
                        float py = (mv.y > 1.f) ? 1.f : 0.f;  mv.y = (mv.y > 1.f) ? 0.f : mv.y;
                        *(__half2*)(spk_out + ix) = __floats2half2_rn(px, py);
                    }
                    *(float2*)(S + ix) = sv;
                    *(float2*)(M + ix) = mv;
                }
    };

#pragma unroll 1
    for (int g = 0; g < 32; g++) {
        if (g <= 29)      CP_WAIT(2);
        else if (g == 30) CP_WAIT(1);
        else              CP_WAIT(0);
        __syncthreads();                       // single barrier per chunk
        if (g + 3 < 32) load_chunk(g + 3);

        const uint32_t ab = sb + (g & 3) * STAGE_BYTES;
        const uint32_t bb = ab + 8192;
#pragma unroll
        for (int k16 = 0; k16 < 2; k16++) {
            const int k0 = k16 * 16;
            uint32_t a[4][4];
#pragma unroll
            for (int mt = 0; mt < 4; mt++) {
                int row = warp_m * 64 + mt * 16 + (mat & 1) * 8 + mrr;
                int kk  = k0 + (mat >> 1) * 8;
                ldm4(a[mt][0], a[mt][1], a[mt][2], a[mt][3],
                     ab + SWZ64(row * 64 + kk * 2));
            }
#pragma unroll
            for (int sp = 0; sp < 2; sp++) {
                uint32_t b[2][4];
#pragma unroll
                for (int n2 = 0; n2 < 2; n2++) {
                    int n  = warp_n * 32 + n2 * 16 + (mat >> 1) * 8 + mrr;
                    int kk = k0 + (mat & 1) * 8;
                    ldm4(b[n2][0], b[n2][1], b[n2][2], b[n2][3],
                         bb + sp * 8192 + SWZ64(n * 64 + kk * 2));
                }
#pragma unroll
                for (int mt = 0; mt < 4; mt++)
#pragma unroll
                    for (int nb = 0; nb < 4; nb++)
                        mma16816(acc[mt][nb], a[mt],
                                 b[nb >> 1][(nb & 1) * 2],
                                 b[nb >> 1][(nb & 1) * 2 + 1]);
            }
        }

        if (g == 15) {
            // tile-0 epilogue; chunks 16-18 (tile 1) already in flight
            epilogue(ybase * 128);
#pragma unroll
            for (int mt = 0; mt < 4; mt++)
#pragma unroll
                for (int nb = 0; nb < 4; nb++)
#pragma unroll
                    for (int e = 0; e < 4; e++) acc[mt][nb][e] = 0.f;
        }
    }
    epilogue((ybase + 2) * 128);
}

// ============================================================
// launch — forked-stream pipeline + overlapped setup (capture-fork safe)
// ============================================================
extern "C" void kernel_launch(void* const* d_in, const int* in_sizes, int n_in,
                              void* d_out, int out_size) {
    (void)in_sizes; (void)n_in; (void)out_size;
    const float* inp = (const float*)d_in[0];   // [16384, 128]
    const float* W0  = (const float*)d_in[1];   // [256, 512]
    const float* W1  = (const float*)d_in[2];   // [512, 512]
    const float* W2  = (const float*)d_in[3];   // [512, 512]
    float* out = (float*)d_out;                 // m2 state [16384, 512]

    static cudaStream_t s2 = nullptr, s3 = nullptr;
    static cudaEvent_t e1[2], e2[2], eFork, ePrep, eA, e0;
    if (s2 == nullptr) {
        cudaStreamCreateWithFlags(&s2, cudaStreamNonBlocking);
        cudaStreamCreateWithFlags(&s3, cudaStreamNonBlocking);
        for (int i = 0; i < 2; i++) {
            cudaEventCreateWithFlags(&e1[i], cudaEventDisableTiming);
            cudaEventCreateWithFlags(&e2[i], cudaEventDisableTiming);
        }
        cudaEventCreateWithFlags(&eFork, cudaEventDisableTiming);
        cudaEventCreateWithFlags(&ePrep, cudaEventDisableTiming);
        cudaEventCreateWithFlags(&eA, cudaEventDisableTiming);
        cudaEventCreateWithFlags(&e0, cudaEventDisableTiming);
        cudaFuncSetAttribute(gemm_mma<1>,
                             cudaFuncAttributeMaxDynamicSharedMemorySize, SMEM_NEED);
        cudaFuncSetAttribute(gemm_mma<2>,
                             cudaFuncAttributeMaxDynamicSharedMemorySize, SMEM_NEED);
    }

    __half* d_spk0all;  cudaGetSymbolAddress((void**)&d_spk0all, g_spk0all);
    __half* d_spk1a;    cudaGetSymbolAddress((void**)&d_spk1a, g_spk1a);
    __half* d_spk1b;    cudaGetSymbolAddress((void**)&d_spk1b, g_spk1b);
    __half* spk1buf[2] = {d_spk1a, d_spk1b};

    // ---- fork point: first captured op, recorded in the ORIGIN stream ----
    zero_kernel<<<(NELEM / 4) / 256, 256>>>((float4*)out);
    cudaEventRecord(eFork, cudaStreamPerThread);

    // s2 joins the capture via waitEvent, THEN launches (capture-fork rule)
    cudaStreamWaitEvent(s2, eFork, 0);
    prep_kernel<1><<<1024, 256, 0, s2>>>(W1);
    prep_kernel<2><<<1024, 256, 0, s2>>>(W2);
    cudaEventRecord(ePrep, s2);

    // main stream: layer-0 drive + head of the spike trajectories
    gemm0_kernel<<<dim3(128, 4), 256>>>(inp, W0);
    spikes0_kernel<0, TSPLIT, true><<<NELEM / 256, 256>>>();
    cudaEventRecord(eA, cudaStreamPerThread);

    // s3 joins via waitEvent, then computes the trajectory tail
    cudaStreamWaitEvent(s3, eA, 0);
    spikes0_kernel<TSPLIT, NSTEP, false><<<NELEM / 256, 256, 0, s3>>>();
    cudaEventRecord(e0, s3);

    cudaStreamWaitEvent(cudaStreamPerThread, ePrep, 0);  // W1t ready for g1

    // ---- main t-loop ----
    dim3 grid(128, 2);
    for (int t = 0; t < NSTEP; t++) {
        const int par = t & 1;
        if (t == TSPLIT)
            cudaStreamWaitEvent(cudaStreamPerThread, e0, 0);
        if (t >= 2)
            cudaStreamWaitEvent(cudaStreamPerThread, e2[par], 0);
        gemm_mma<1><<<grid, 256, SMEM_NEED>>>(
            d_spk0all + (size_t)t * NELEM, spk1buf[par], nullptr);
        cudaEventRecord(e1[par], cudaStreamPerThread);
        cudaStreamWaitEvent(s2, e1[par], 0);
        gemm_mma<2><<<grid, 256, SMEM_NEED, s2>>>(spk1buf[par], nullptr, out);
        cudaEventRecord(e2[par], s2);
    }
    cudaStreamWaitEvent(cudaStreamPerThread, e2[0], 0);
    cudaStreamWaitEvent(cudaStreamPerThread, e2[1], 0);
}

// round 15
// speedup vs baseline: 1.1631x; 1.1631x over previous
#include <cuda_runtime.h>
#include <cuda_fp16.h>
#include <cstdint>

// ============================================================
// 3-layer SNN. B=16384, H=512, 127 steps.
// R15 = R13 (best: 16.7ms) + 4-deep spk1 ring (parity t&3) so g1(t) only
// waits g2(t-4) instead of g2(t-2) -> relaxes the cross-stream dependency
// chain, letting the scheduler absorb stragglers/ragged waves.
//  - overlapped setup (W-prep on s2, spikes0 tail on s3, capture-fork safe)
//  - forked-stream t-loop: g2(t) on s2 overlaps g1(t+1)
//  - 2 exact fp16 W-splits on mma.sync m16n8k16, fp32 accum
// Expect bit-identical rel_err 1.011837e-4.
// ============================================================

constexpr int NSTEP = 127;
constexpr int TSPLIT = 8;              // spikes0 split point
constexpr int NELEM = 16384 * 512;

__device__ float g_h0[NELEM];
__device__ float g_mc[NELEM];          // layer-0 membrane carry at t=TSPLIT
__device__ float g_s1[NELEM];
__device__ float g_m1[NELEM];
__device__ float g_s2[NELEM];
__device__ __half g_spk0all[(size_t)NSTEP * NELEM];   // 2.13GB
__device__ __half g_spk1r[4][NELEM];                  // 4-deep spk1 ring
__device__ __half g_W1t[2][512 * 512];   // [split][N][K] K-contiguous
__device__ __half g_W2t[2][512 * 512];

// ---- PTX helpers (sm_80-class, valid at sm_103 base target) ----
__device__ __forceinline__ uint32_t smem_to_u32(const void* p) {
    uint32_t a;
    asm("{ .reg .u64 t; cvta.to.shared.u64 t, %1; cvt.u32.u64 %0, t; }"
        : "=r"(a) : "l"(p));
    return a;
}
__device__ __forceinline__ void cp16(uint32_t dst, const void* src) {
    asm volatile("cp.async.cg.shared.global [%0], [%1], 16;"
                 :: "r"(dst), "l"(src) : "memory");
}
#define CP_COMMIT() asm volatile("cp.async.commit_group;" ::: "memory")
#define CP_WAIT(N)  asm volatile("cp.async.wait_group %0;" :: "n"(N) : "memory")
__device__ __forceinline__ void l2_prefetch(const void* p) {
    asm volatile("prefetch.global.L2 [%0];" :: "l"(p));
}

__device__ __forceinline__ void ldm4(uint32_t& r0, uint32_t& r1, uint32_t& r2,
                                     uint32_t& r3, uint32_t addr) {
    asm volatile("ldmatrix.sync.aligned.m8n8.x4.shared.b16 {%0,%1,%2,%3}, [%4];"
                 : "=r"(r0), "=r"(r1), "=r"(r2), "=r"(r3) : "r"(addr));
}
__device__ __forceinline__ void mma16816(float* c, const uint32_t* a,
                                         uint32_t b0, uint32_t b1) {
    asm volatile(
        "mma.sync.aligned.m16n8k16.row.col.f32.f16.f16.f32 "
        "{%0,%1,%2,%3}, {%4,%5,%6,%7}, {%8,%9}, {%0,%1,%2,%3};"
        : "+f"(c[0]), "+f"(c[1]), "+f"(c[2]), "+f"(c[3])
        : "r"(a[0]), "r"(a[1]), "r"(a[2]), "r"(a[3]), "r"(b0), "r"(b1));
}
#define SWZ64(x) ((x) ^ (((x) >> 3) & 0x30))

// ============================================================
// one-time kernels
// ============================================================
__global__ void zero_kernel(float4* __restrict__ out) {
    int i = blockIdx.x * blockDim.x + threadIdx.x;
    float4 z = make_float4(0.f, 0.f, 0.f, 0.f);
    ((float4*)g_s1)[i] = z;
    ((float4*)g_m1)[i] = z;
    ((float4*)g_s2)[i] = z;
    out[i] = z;
}

// exact 2-way fp16 split + transpose of W [512K x 512N] -> Wt[2][N][K]
template <int WHICH>
__global__ void prep_kernel(const float* __restrict__ Wsrc) {
    int idx = blockIdx.x * blockDim.x + threadIdx.x;  // over 512*512
    int k = idx >> 9, n = idx & 511;
    float w = Wsrc[idx];
    __half hi = __float2half_rn(w);
    __half lo = __float2half_rn(w - __half2float(hi));
    __half (*dst)[512 * 512] = (WHICH == 1) ? g_W1t : g_W2t;
    int t = n * 512 + k;
    dst[0][t] = hi;
    dst[1][t] = lo;
}

// layer-0 LIF trajectories, t in [T0, T1). PART A writes the carry;
// PART B resumes from it — identical per-element arithmetic.
template <int T0, int T1, bool WRITE_CARRY>
__global__ void spikes0_kernel() {
    int idx = blockIdx.x * blockDim.x + threadIdx.x;  // over NELEM
    float h = g_h0[idx];
    float m = (T0 == 0) ? 0.f : g_mc[idx];
#pragma unroll 1
    for (int t = T0; t < T1; t++) {
        m = 0.85f * m + h;
        bool p = m > 1.0f;
        g_spk0all[(size_t)t * NELEM + idx] = p ? __float2half(1.f)
                                               : __float2half(0.f);
        if (p) m = 0.f;
    }
    if (WRITE_CARRY) g_mc[idx] = m;
}

// ============================================================
// layer-0 drive: h0 = relu_concat(inputs) @ W0 (fp32, runs once)
// ============================================================
__global__ __launch_bounds__(256)
void gemm0_kernel(const float* __restrict__ Aext, const float* __restrict__ W) {
    constexpr int KT = 8, NK = 256 / KT;
    __shared__ float As[2][KT][128];
    __shared__ float Bs[2][KT][128];
    const int row0 = blockIdx.x * 128, col0 = blockIdx.y * 128;
    const int tid = threadIdx.x;
    const int tx = tid & 15, ty = tid >> 4;
    const int ar = tid >> 1, aq = (tid & 1) * 4;
    const int bk = tid >> 5, bj = (tid & 31) * 4;

    float acc[8][8];
#pragma unroll
    for (int i = 0; i < 8; i++)
#pragma unroll
        for (int j = 0; j < 8; j++) acc[i][j] = 0.f;

    float4 ra, rb;
    auto LOADG = [&](int k0) {
        int kk = k0 + aq;
        if (kk < 128) {
            float4 v = *(const float4*)(Aext + (size_t)(row0 + ar) * 128 + kk);
            ra.x = fmaxf(v.x, 0.f); ra.y = fmaxf(v.y, 0.f);
            ra.z = fmaxf(v.z, 0.f); ra.w = fmaxf(v.w, 0.f);
        } else {
            float4 v = *(const float4*)(Aext + (size_t)(row0 + ar) * 128 + (kk - 128));
            ra.x = fmaxf(-v.x, 0.f); ra.y = fmaxf(-v.y, 0.f);
            ra.z = fmaxf(-v.z, 0.f); ra.w = fmaxf(-v.w, 0.f);
        }
        rb = *(const float4*)(W + (size_t)(k0 + bk) * 512 + col0 + bj);
    };
    auto STORES = [&](int buf) {
        As[buf][aq + 0][ar] = ra.x; As[buf][aq + 1][ar] = ra.y;
        As[buf][aq + 2][ar] = ra.z; As[buf][aq + 3][ar] = ra.w;
        *(float4*)&Bs[buf][bk][bj] = rb;
    };

    LOADG(0); STORES(0); __syncthreads();
    for (int kt = 0; kt < NK; kt++) {
        const int buf = kt & 1;
        if (kt + 1 < NK) LOADG((kt + 1) * KT);
#pragma unroll
        for (int k = 0; k < KT; k++) {
            float4 a0 = *(const float4*)&As[buf][k][ty * 8];
            float4 a1 = *(const float4*)&As[buf][k][ty * 8 + 4];
            float4 b0 = *(const float4*)&Bs[buf][k][tx * 8];
            float4 b1 = *(const float4*)&Bs[buf][k][tx * 8 + 4];
            float av[8] = {a0.x, a0.y, a0.z, a0.w, a1.x, a1.y, a1.z, a1.w};
            float bv[8] = {b0.x, b0.y, b0.z, b0.w, b1.x, b1.y, b1.z, b1.w};
#pragma unroll
            for (int i = 0; i < 8; i++)
#pragma unroll
                for (int j = 0; j < 8; j++) acc[i][j] = fmaf(av[i], bv[j], acc[i][j]);
        }
        if (kt + 1 < NK) STORES(buf ^ 1);
        __syncthreads();
    }
    const int r0 = row0 + ty * 8, c0 = col0 + tx * 8;
#pragma unroll
    for (int i = 0; i < 8; i++) {
        size_t base = (size_t)(r0 + i) * 512 + c0;
        *(float4*)&g_h0[base]     = make_float4(acc[i][0], acc[i][1], acc[i][2], acc[i][3]);
        *(float4*)&g_h0[base + 4] = make_float4(acc[i][4], acc[i][5], acc[i][6], acc[i][7]);
    }
}

// ============================================================
// HMMA GEMM + fused LIF epilogue  (R13 mainloop, unchanged)
// Tile M=128 x N=128; K=512 in 16 chunks of 32; 2 fp16 W-splits.
// 4-stage cp.async pipeline (prefetch depth 3, wait_group 2), one barrier
// per chunk. SW64. 8 warps, warp tile 64x32. S/M tiles L2-prefetched.
// ============================================================
constexpr int STAGE_BYTES = 24576;
constexpr int SMEM_NEED   = 4 * STAGE_BYTES;   // 96KB -> 2 CTAs/SM

template <int MODE>
__global__ __launch_bounds__(256, 2)
void gemm_mma(const __half* __restrict__ A, __half* __restrict__ spk_out,
              float* __restrict__ Mext) {
    extern __shared__ char smem[];
    const int tid = threadIdx.x;
    const int wid = tid >> 5, lane = tid & 31;
    const int warp_m = wid & 1, warp_n = wid >> 1;
    const int row0 = blockIdx.x * 128, col0 = blockIdx.y * 128;

    const __half* W = (MODE == 1) ? &g_W1t[0][0] : &g_W2t[0][0];
    const uint32_t sb = smem_to_u32(smem);

    auto load_chunk = [&](int c, int s) {
        const uint32_t ap = sb + s * STAGE_BYTES;
        const uint32_t bp = ap + 8192;
        const int k0 = c * 32;
#pragma unroll
        for (int j = 0; j < 2; j++) {                  // A: 512 x 16B
            int i = tid + j * 256;
            int r = i >> 2, q = i & 3;
            cp16(ap + SWZ64(r * 64 + q * 16),
                 A + (size_t)(row0 + r) * 512 + k0 + q * 8);
        }
#pragma unroll
        for (int j = 0; j < 4; j++) {                  // B: 2 x 512 x 16B
            int i = tid + j * 256;
            int sp = i >> 9, rem = i & 511;
            int n = rem >> 2, q = rem & 3;
            cp16(bp + sp * 8192 + SWZ64(n * 64 + q * 16),
                 W + (size_t)sp * 262144 + (size_t)(col0 + n) * 512 + k0 + q * 8);
        }
        CP_COMMIT();
    };

    load_chunk(0, 0);
    load_chunk(1, 1);
    load_chunk(2, 2);

    // warm L2 with this tile's epilogue state (row tid>>1, 64-col half tid&1)
    {
        const float* S = (MODE == 1) ? g_s1 : g_s2;
        const float* M = (MODE == 1) ? g_m1 : Mext;
        size_t pix = (size_t)(row0 + (tid >> 1)) * 512 + col0 + (tid & 1) * 64;
        l2_prefetch(S + pix);  l2_prefetch(S + pix + 32);
        l2_prefetch(M + pix);  l2_prefetch(M + pix + 32);
    }

    float acc[4][4][4];
#pragma unroll
    for (int mt = 0; mt < 4; mt++)
#pragma unroll
        for (int nb = 0; nb < 4; nb++)
#pragma unroll
            for (int e = 0; e < 4; e++) acc[mt][nb][e] = 0.f;

    const int mat = lane >> 3, mrr = lane & 7;

#pragma unroll 1
    for (int c = 0; c < 16; c++) {
        const int s = c & 3;
        if (c <= 13)      CP_WAIT(2);
        else if (c == 14) CP_WAIT(1);
        else              CP_WAIT(0);
        __syncthreads();                       // single barrier per chunk
        if (c + 3 < 16) load_chunk(c + 3, (c + 3) & 3);

        const uint32_t ab = sb + s * STAGE_BYTES;
        const uint32_t bb = ab + 8192;
#pragma unroll
        for (int k16 = 0; k16 < 2; k16++) {
            const int k0 = k16 * 16;
            uint32_t a[4][4];
#pragma unroll
            for (int mt = 0; mt < 4; mt++) {
                int row = warp_m * 64 + mt * 16 + (mat & 1) * 8 + mrr;
                int kk  = k0 + (mat >> 1) * 8;
                ldm4(a[mt][0], a[mt][1], a[mt][2], a[mt][3],
                     ab + SWZ64(row * 64 + kk * 2));
            }
#pragma unroll
            for (int sp = 0; sp < 2; sp++) {
                uint32_t b[2][4];
#pragma unroll
                for (int n2 = 0; n2 < 2; n2++) {
                    int n  = warp_n * 32 + n2 * 16 + (mat >> 1) * 8 + mrr;
                    int kk = k0 + (mat & 1) * 8;
                    ldm4(b[n2][0], b[n2][1], b[n2][2], b[n2][3],
                         bb + sp * 8192 + SWZ64(n * 64 + kk * 2));
                }
#pragma unroll
                for (int mt = 0; mt < 4; mt++)
#pragma unroll
                    for (int nb = 0; nb < 4; nb++)
                        mma16816(acc[mt][nb], a[mt],
                                 b[nb >> 1][(nb & 1) * 2],
                                 b[nb >> 1][(nb & 1) * 2 + 1]);
            }
        }
    }

    // ---- fused LIF epilogue, direct from mma fragments ----
    float* S = (MODE == 1) ? g_s1 : g_s2;
    float* M = (MODE == 1) ? g_m1 : Mext;
    const int er = row0 + warp_m * 64 + (lane >> 2);
    const int ec = col0 + warp_n * 32 + (lane & 3) * 2;
#pragma unroll
    for (int mt = 0; mt < 4; mt++)
#pragma unroll
        for (int nb = 0; nb < 4; nb++)
#pragma unroll
            for (int hrow = 0; hrow < 2; hrow++) {
                size_t ix = (size_t)(er + mt * 16 + hrow * 8) * 512 + ec + nb * 8;
                float2 sv = *(const float2*)(S + ix);
                float2 mv = *(const float2*)(M + ix);
                float hx = acc[mt][nb][hrow * 2 + 0];
                float hy = acc[mt][nb][hrow * 2 + 1];
                sv.x = 0.9f * sv.x + hx;  mv.x = 0.85f * mv.x + sv.x;
                sv.y = 0.9f * sv.y + hy;  mv.y = 0.85f * mv.y + sv.y;
                if (MODE == 1) {
                    float px = (mv.x > 1.f) ? 1.f : 0.f;  mv.x = (mv.x > 1.f) ? 0.f : mv.x;
                    float py = (mv.y > 1.f) ? 1.f : 0.f;  mv.y = (mv.y > 1.f) ? 0.f : mv.y;
                    *(__half2*)(spk_out + ix) = __floats2half2_rn(px, py);
                }
                *(float2*)(S + ix) = sv;
                *(float2*)(M + ix) = mv;
            }
}

// ============================================================
// launch — forked-stream pipeline + overlapped setup (capture-fork safe),
// 4-deep spk1 ring: g1(t) waits g2(t-4); g2(t) waits g1(t).
// ============================================================
extern "C" void kernel_launch(void* const* d_in, const int* in_sizes, int n_in,
                              void* d_out, int out_size) {
    (void)in_sizes; (void)n_in; (void)out_size;
    const float* inp = (const float*)d_in[0];   // [16384, 128]
    const float* W0  = (const float*)d_in[1];   // [256, 512]
    const float* W1  = (const float*)d_in[2];   // [512, 512]
    const float* W2  = (const float*)d_in[3];   // [512, 512]
    float* out = (float*)d_out;                 // m2 state [16384, 512]

    static cudaStream_t s2 = nullptr, s3 = nullptr;
    static cudaEvent_t e1[4], e2[4], eFork, ePrep, eA, e0;
    if (s2 == nullptr) {
        cudaStreamCreateWithFlags(&s2, cudaStreamNonBlocking);
        cudaStreamCreateWithFlags(&s3, cudaStreamNonBlocking);
        for (int i = 0; i < 4; i++) {
            cudaEventCreateWithFlags(&e1[i], cudaEventDisableTiming);
            cudaEventCreateWithFlags(&e2[i], cudaEventDisableTiming);
        }
        cudaEventCreateWithFlags(&eFork, cudaEventDisableTiming);
        cudaEventCreateWithFlags(&ePrep, cudaEventDisableTiming);
        cudaEventCreateWithFlags(&eA, cudaEventDisableTiming);
        cudaEventCreateWithFlags(&e0, cudaEventDisableTiming);
        cudaFuncSetAttribute(gemm_mma<1>,
                             cudaFuncAttributeMaxDynamicSharedMemorySize, SMEM_NEED);
        cudaFuncSetAttribute(gemm_mma<2>,
                             cudaFuncAttributeMaxDynamicSharedMemorySize, SMEM_NEED);
    }

    __half* d_spk0all;  cudaGetSymbolAddress((void**)&d_spk0all, g_spk0all);
    __half* d_spk1r;    cudaGetSymbolAddress((void**)&d_spk1r, g_spk1r);
    __half* spk1buf[4] = {d_spk1r, d_spk1r + NELEM,
                          d_spk1r + 2 * (size_t)NELEM, d_spk1r + 3 * (size_t)NELEM};

    // ---- fork point: first captured op, recorded in the ORIGIN stream ----
    zero_kernel<<<(NELEM / 4) / 256, 256>>>((float4*)out);
    cudaEventRecord(eFork, cudaStreamPerThread);

    // s2 joins the capture via waitEvent, THEN launches (capture-fork rule)
    cudaStreamWaitEvent(s2, eFork, 0);
    prep_kernel<1><<<1024, 256, 0, s2>>>(W1);
    prep_kernel<2><<<1024, 256, 0, s2>>>(W2);
    cudaEventRecord(ePrep, s2);

    // main stream: layer-0 drive + head of the spike trajectories
    gemm0_kernel<<<dim3(128, 4), 256>>>(inp, W0);
    spikes0_kernel<0, TSPLIT, true><<<NELEM / 256, 256>>>();
    cudaEventRecord(eA, cudaStreamPerThread);

    // s3 joins via waitEvent, then computes the trajectory tail
    cudaStreamWaitEvent(s3, eA, 0);
    spikes0_kernel<TSPLIT, NSTEP, false><<<NELEM / 256, 256, 0, s3>>>();
    cudaEventRecord(e0, s3);

    cudaStreamWaitEvent(cudaStreamPerThread, ePrep, 0);  // W1t ready for g1

    // ---- main t-loop ----
    dim3 grid(128, 4);
    for (int t = 0; t < NSTEP; t++) {
        const int par = t & 3;
        if (t == TSPLIT)
            cudaStreamWaitEvent(cudaStreamPerThread, e0, 0);
        if (t >= 4)
            cudaStreamWaitEvent(cudaStreamPerThread, e2[par], 0);
        gemm_mma<1><<<grid, 256, SMEM_NEED>>>(
            d_spk0all + (size_t)t * NELEM, spk1buf[par], nullptr);
        cudaEventRecord(e1[par], cudaStreamPerThread);
        cudaStreamWaitEvent(s2, e1[par], 0);
        gemm_mma<2><<<grid, 256, SMEM_NEED, s2>>>(spk1buf[par], nullptr, out);
        cudaEventRecord(e2[par], s2);
    }
    for (int i = 0; i < 4; i++)
        cudaStreamWaitEvent(cudaStreamPerThread, e2[i], 0);
}